// round 10
// baseline (speedup 1.0000x reference)
#include <cuda_runtime.h>

// Problem constants (fixed by the reference)
#define B     32
#define N     2048
#define OUTD  100
#define BPG   4                     // batch rows per block
#define OG    10                    // output columns per block
#define BGROUPS (B / BPG)           // 8
#define OGROUPS (OUTD / OG)         // 10
#define GRID  (BGROUPS * OGROUPS)   // 80 blocks, single wave on 148 SMs
#define NT    512
#define NW    16

// out[b,o] = sum_j rem[b,j] * W[j,o]
// rem[b,j] = (q[b,j] - float(N*c[b,j] + S_b))^2, c = (int)q, S_b = sum_j c[b,j]
// Exact vs reference: all integer partials < 2^24, so the reference's fp32
// reduce of the [N,N] broadcast equals the int32 closed form bit-for-bit.
//
// Partition: block = (4 batch rows) x (10 output cols). Every block is fully
// self-contained: local S reduce, rem in registers, direct out stores.
// No split-K partials, no threadfence, no atomics, no last-block drain.

__global__ __launch_bounds__(NT, 1)
void fused_rowstat_direct_kernel(const float* __restrict__ q,
                                 const float* __restrict__ W,
                                 float* __restrict__ out)
{
    __shared__ int   qsum[NW];
    __shared__ float partial[NW][OG];     // per-warp output partials (640 B)

    const int tid  = threadIdx.x;
    const int wid  = tid >> 5;
    const int lane = tid & 31;
    const int bg   = blockIdx.x / OGROUPS;      // batch group 0..7
    const int og   = blockIdx.x - bg * OGROUPS; // output group 0..9
    const int o0   = og * OG;

    const int r = tid >> 7;               // row within group (warps 4r..4r+3)
    const int t = tid & 127;              // position within the row's threads

    // ---- Phase 1: load this block's 4 q rows (4 float4 / thread), keep in
    //      registers, and reduce the int row sums locally. ----
    float4 v[4];
    {
        const float4* q4 = reinterpret_cast<const float4*>(q + (bg * BPG + r) * N);
        int ss = 0;
        #pragma unroll
        for (int i = 0; i < 4; ++i) {
            v[i] = q4[t + 128 * i];
            ss += (int)v[i].x + (int)v[i].y + (int)v[i].z + (int)v[i].w;
        }
        ss = __reduce_add_sync(0xFFFFFFFFu, ss);     // REDUX.SUM
        if (lane == 0) qsum[wid] = ss;
    }
    __syncthreads();
    const int S = qsum[4*r] + qsum[4*r+1] + qsum[4*r+2] + qsum[4*r+3];

    // ---- Phase 2: rem for this thread's 16 j's, in registers ----
    float rem[16];
    #pragma unroll
    for (int i = 0; i < 4; ++i) {
        const float* vf = reinterpret_cast<const float*>(&v[i]);
        #pragma unroll
        for (int k = 0; k < 4; ++k) {
            float qv = vf[k];
            int   c  = (int)qv;                       // trunc == astype(int32)
            float d  = qv - (float)(N * c + S);
            rem[i * 4 + k] = d * d;
        }
    }

    // ---- Phase 3: partial dot products over this thread's 16 j's for the
    //      block's 10 outputs. W rows at 8B-aligned offsets -> LDG.64. ----
    float acc[OG];
    #pragma unroll
    for (int m = 0; m < OG; ++m) acc[m] = 0.f;

    #pragma unroll
    for (int i = 0; i < 4; ++i) {
        const int jbase = (t + 128 * i) * 4;
        #pragma unroll
        for (int k = 0; k < 4; ++k) {
            const int   j  = jbase + k;
            const float rv = rem[i * 4 + k];
            const float2* Wp = reinterpret_cast<const float2*>(W + (size_t)j * OUTD + o0);
            #pragma unroll
            for (int m = 0; m < OG / 2; ++m) {        // 5 independent LDG.64
                float2 w = Wp[m];
                acc[2*m + 0] = fmaf(rv, w.x, acc[2*m + 0]);
                acc[2*m + 1] = fmaf(rv, w.y, acc[2*m + 1]);
            }
        }
    }

    // ---- Phase 4: warp shfl-tree (10 independent chains), smem combine ----
    #pragma unroll
    for (int m = 0; m < OG; ++m) {
        float a = acc[m];
        #pragma unroll
        for (int off = 16; off > 0; off >>= 1)
            a += __shfl_xor_sync(0xFFFFFFFFu, a, off);
        if (lane == 0) partial[wid][m] = a;
    }
    __syncthreads();

    if (tid < BPG * OG) {                             // 40 threads
        const int rr = tid / OG;
        const int m  = tid - rr * OG;
        float s = partial[4*rr][m] + partial[4*rr+1][m]
                + partial[4*rr+2][m] + partial[4*rr+3][m];
        out[(bg * BPG + rr) * OUTD + o0 + m] = s;
    }
}

extern "C" void kernel_launch(void* const* d_in, const int* in_sizes, int n_in,
                              void* d_out, int out_size)
{
    const float* q = (const float*)d_in[0];   // [32, 2048] f32
    const float* W = (const float*)d_in[1];   // [2048, 100] f32
    float* out = (float*)d_out;               // [32, 100] f32
    (void)in_sizes; (void)n_in; (void)out_size;

    fused_rowstat_direct_kernel<<<GRID, NT>>>(q, W, out);
}

// round 11
// speedup vs baseline: 2.0627x; 2.0627x over previous
#include <cuda_runtime.h>

// Problem constants (fixed by the reference)
#define B       32
#define N       2048
#define OUTD    100
#define JSPLITS 16
#define JCHUNK  (N / JSPLITS)        // 128
#define BPG     4                    // batch rows per block (W register reuse)
#define BGROUPS (B / BPG)            // 8
#define GRID    (JSPLITS * BGROUPS)  // 128 blocks
#define NT      512
#define NW      16
#define J_PER_WARP (JCHUNK / NW)     // 8

// out[b,o] = sum_j rem[b,j] * W[j,o]
// rem[b,j] = (q[b,j] - float(N*c[b,j] + S_b))^2, c = (int)q, S_b = sum_j c[b,j]
// Exact vs reference: all integer partials < 2^24, so the reference's fp32
// reduce of the [N,N] broadcast equals the int32 closed form bit-for-bit.
//
// Tail: no split-K partial buffers, no threadfence, no counter, no drain.
// out is zeroed by a memset graph node; each block contributes its split's
// 400 partials via fire-and-forget red.global.add.f32 (RED, no return path).
// Each split partial is itself a fixed-order sum; cross-split add ordering
// perturbs results only at the ~1e-7 level, far inside the 1e-3 gate.

__global__ __launch_bounds__(NT, 1)
void fused_rowstat_gemv_kernel(const float* __restrict__ q,
                               const float* __restrict__ W,
                               float* __restrict__ out)
{
    __shared__ float4 rem4[BPG][JCHUNK / 4];     // 2 KB
    __shared__ float  part_sh[NW][BPG * OUTD];   // 25.6 KB
    __shared__ int    qsum[NW];

    const int tid  = threadIdx.x;
    const int wid  = tid >> 5;
    const int lane = tid & 31;
    const int s    = blockIdx.x & (JSPLITS - 1);   // j-split index
    const int bg   = blockIdx.x >> 4;              // batch-group index
    const int j0   = s * JCHUNK;

    // ---- Prefetch W into registers (block-index-dependent only). These
    //      8 independent, fully-coalesced LDG.128 retire behind phase 1. ----
    const int g  = lane;                 // output group: o = 4g..4g+3 (g<25)
    const int jw = wid * J_PER_WARP;
    float4 w4[J_PER_WARP];
    if (g < 25) {
        const float* Wg = W + (size_t)(j0 + jw) * OUTD + g * 4;
        #pragma unroll
        for (int jj = 0; jj < J_PER_WARP; ++jj)
            w4[jj] = *reinterpret_cast<const float4*>(Wg + jj * OUTD);
    }

    // ---- Phase 1: int row-sums for the 4 rows (4 warps per row), and keep
    //      the float4 that belongs to this block's j-chunk in a register. ----
    const int r       = wid >> 2;                  // row within group
    const int quarter = wid & 3;
    const int i_need  = s >> 2;                    // unroll step holding chunk s
    const bool owns_chunk = (quarter == (s & 3));
    float4 vkeep;
    {
        const float4* q4 = reinterpret_cast<const float4*>(q + (bg * BPG + r) * N);
        const int t = quarter * 32 + lane;         // 0..127
        int ss = 0;
        #pragma unroll
        for (int i = 0; i < 4; ++i) {
            float4 v = q4[t + 128 * i];
            ss += (int)v.x + (int)v.y + (int)v.z + (int)v.w;
            if (i == i_need) vkeep = v;
        }
        ss = __reduce_add_sync(0xFFFFFFFFu, ss);   // REDUX.SUM
        if (lane == 0) qsum[wid] = ss;
    }
    __syncthreads();

    // ---- Phase 2: rem chunk straight from registers; owner warps read the
    //      four per-warp sums via broadcast LDS (no extra barrier round). ----
    if (owns_chunk) {
        const int   S = qsum[4*r] + qsum[4*r+1] + qsum[4*r+2] + qsum[4*r+3];
        const float4 v = vkeep;
        int   c0 = (int)v.x, c1 = (int)v.y, c2 = (int)v.z, c3 = (int)v.w;
        float d0 = v.x - (float)(N * c0 + S);
        float d1 = v.y - (float)(N * c1 + S);
        float d2 = v.z - (float)(N * c2 + S);
        float d3 = v.w - (float)(N * c3 + S);
        rem4[r][lane] = make_float4(d0*d0, d1*d1, d2*d2, d3*d3);
    }
    __syncthreads();

    // ---- Phase 3: GEMV on registers + smem broadcast (measured-best form) ----
    if (g < 25) {
        const float* rem = reinterpret_cast<const float*>(&rem4[0][0]);
        float acc[BPG][4];
        #pragma unroll
        for (int rr = 0; rr < BPG; ++rr)
            acc[rr][0] = acc[rr][1] = acc[rr][2] = acc[rr][3] = 0.f;
        #pragma unroll
        for (int jj = 0; jj < J_PER_WARP; ++jj) {
            #pragma unroll
            for (int rr = 0; rr < BPG; ++rr) {
                float rv = rem[rr * JCHUNK + jw + jj];
                acc[rr][0] = fmaf(rv, w4[jj].x, acc[rr][0]);
                acc[rr][1] = fmaf(rv, w4[jj].y, acc[rr][1]);
                acc[rr][2] = fmaf(rv, w4[jj].z, acc[rr][2]);
                acc[rr][3] = fmaf(rv, w4[jj].w, acc[rr][3]);
            }
        }
        #pragma unroll
        for (int rr = 0; rr < BPG; ++rr)
            *reinterpret_cast<float4*>(&part_sh[wid][rr * OUTD + g * 4]) =
                make_float4(acc[rr][0], acc[rr][1], acc[rr][2], acc[rr][3]);
    }
    __syncthreads();

    // ---- Phase 4: reduce 16 warps, then fire-and-forget RED into out ----
    if (tid < BPG * OUTD) {                        // 400 of 512 threads
        float ssum = 0.f;
        #pragma unroll
        for (int w = 0; w < NW; ++w) ssum += part_sh[w][tid];
        const int rr = tid / OUTD;
        const int o  = tid - rr * OUTD;
        // RED.ADD.F32, no return, no fence, no waiting.
        atomicAdd(&out[(bg * BPG + rr) * OUTD + o], ssum);
    }
}

extern "C" void kernel_launch(void* const* d_in, const int* in_sizes, int n_in,
                              void* d_out, int out_size)
{
    const float* q = (const float*)d_in[0];   // [32, 2048] f32
    const float* W = (const float*)d_in[1];   // [2048, 100] f32
    float* out = (float*)d_out;               // [32, 100] f32
    (void)in_sizes; (void)n_in; (void)out_size;

    // Zero the accumulation target (graph-capturable memset node).
    cudaMemsetAsync(out, 0, (size_t)B * OUTD * sizeof(float));
    fused_rowstat_gemv_kernel<<<GRID, NT>>>(q, W, out);
}